// round 5
// baseline (speedup 1.0000x reference)
#include <cuda_runtime.h>

// Device-global scratch (no allocations). Zero-init at load; last block resets
// after writing out, so graph replays stay deterministic.
__device__ unsigned long long g_mismatch_count = 0ULL;
__device__ unsigned int g_blocks_arrived = 0u;

__device__ __forceinline__ int group_of(int c) {
    return (c < 3) ? 0 : ((c < 6) ? 1 : 2);
}

__device__ __forceinline__ int argmax8(float4 a, float4 b) {
    float m = a.x; int am = 0;
    if (a.y > m) { m = a.y; am = 1; }
    if (a.z > m) { m = a.z; am = 2; }
    if (a.w > m) { m = a.w; am = 3; }
    if (b.x > m) { m = b.x; am = 4; }
    if (b.y > m) { m = b.y; am = 5; }
    if (b.z > m) { m = b.z; am = 6; }
    if (b.w > m) { m = b.w; am = 7; }
    return am;
}

__global__ void __launch_bounds__(256) path_loss_fused_kernel(
    const float4* __restrict__ preds,   // [batch * 2] float4
    const int* __restrict__ targets,    // [batch] int32
    float* __restrict__ out,
    int batch)
{
    int gid = blockIdx.x * blockDim.x + threadIdx.x;
    int nthreads = gridDim.x * blockDim.x;
    int nquads = batch >> 2;            // rows processed 4 at a time

    unsigned int local = 0;

    // Each thread owns 4 consecutive rows per quad-iteration; all 9 loads are
    // issued up front (8x float4 preds + 1x int4 targets) for high MLP.
    for (int q = gid; q < nquads; q += nthreads) {
        int r = q << 2;
        const float4* p = preds + 2 * r;   // 8 consecutive float4s = 128B
        float4 a0 = p[0], b0 = p[1];
        float4 a1 = p[2], b1 = p[3];
        float4 a2 = p[4], b2 = p[5];
        float4 a3 = p[6], b3 = p[7];
        int4 t = *(const int4*)(targets + r);

        local += (group_of(argmax8(a0, b0)) != group_of(t.x)) ? 1u : 0u;
        local += (group_of(argmax8(a1, b1)) != group_of(t.y)) ? 1u : 0u;
        local += (group_of(argmax8(a2, b2)) != group_of(t.z)) ? 1u : 0u;
        local += (group_of(argmax8(a3, b3)) != group_of(t.w)) ? 1u : 0u;
    }

    // Tail rows (batch % 4) handled by thread 0 — batch is 4M so normally empty.
    if (gid == 0) {
        for (int i = nquads << 2; i < batch; i++) {
            float4 a = preds[2 * i], b = preds[2 * i + 1];
            local += (group_of(argmax8(a, b)) != group_of(targets[i])) ? 1u : 0u;
        }
    }

    // warp reduction
    #pragma unroll
    for (int off = 16; off > 0; off >>= 1)
        local += __shfl_down_sync(0xFFFFFFFFu, local, off);

    __shared__ unsigned int warp_sums[8];
    int lane = threadIdx.x & 31;
    int wid = threadIdx.x >> 5;
    if (lane == 0) warp_sums[wid] = local;
    __syncthreads();

    if (wid == 0) {
        unsigned int v = (lane < (blockDim.x >> 5)) ? warp_sums[lane] : 0u;
        #pragma unroll
        for (int off = 4; off > 0; off >>= 1)
            v += __shfl_down_sync(0xFFFFFFFFu, v, off);

        if (lane == 0) {
            atomicAdd(&g_mismatch_count, (unsigned long long)v);
            __threadfence();
            unsigned int ticket = atomicAdd(&g_blocks_arrived, 1u);
            if (ticket == gridDim.x - 1) {
                unsigned long long total = atomicAdd(&g_mismatch_count, 0ULL);
                *out = (float)((double)total / (double)batch);
                g_mismatch_count = 0ULL;
                g_blocks_arrived = 0u;
            }
        }
    }
}

extern "C" void kernel_launch(void* const* d_in, const int* in_sizes, int n_in,
                              void* d_out, int out_size) {
    const float4* preds = (const float4*)d_in[0];   // [B, 8] f32
    const int* targets = (const int*)d_in[1];       // [B] int32
    int batch = in_sizes[0] / 8;
    float* out = (float*)d_out;

    const int threads = 256;
    int blocks = 4096;   // 1M threads, exactly 1 quad (4 rows) each at B = 4.19M
    path_loss_fused_kernel<<<blocks, threads>>>(preds, targets, out, batch);
}

// round 6
// speedup vs baseline: 1.3493x; 1.3493x over previous
#include <cuda_runtime.h>

// Device-global scratch (no allocations). Zero-init at load; last block resets
// after writing out, so graph replays stay deterministic.
__device__ unsigned long long g_mismatch_count = 0ULL;
__device__ unsigned int g_blocks_arrived = 0u;

__device__ __forceinline__ int group_of(int c) {
    return (c < 3) ? 0 : ((c < 6) ? 1 : 2);
}

__device__ __forceinline__ unsigned int mismatch(float4 a, float4 b, int t) {
    float m = a.x; int am = 0;
    if (a.y > m) { m = a.y; am = 1; }
    if (a.z > m) { m = a.z; am = 2; }
    if (a.w > m) { m = a.w; am = 3; }
    if (b.x > m) { m = b.x; am = 4; }
    if (b.y > m) { m = b.y; am = 5; }
    if (b.z > m) { m = b.z; am = 6; }
    if (b.w > m) { m = b.w; am = 7; }
    return (group_of(am) != group_of(t)) ? 1u : 0u;
}

__global__ void __launch_bounds__(256) path_loss_fused_kernel(
    const float4* __restrict__ preds,   // [batch * 2] float4 (row = 2 float4s, 32B)
    const int* __restrict__ targets,    // [batch] int32
    float* __restrict__ out,
    int batch)
{
    int gid = blockIdx.x * blockDim.x + threadIdx.x;
    int S = gridDim.x * blockDim.x;     // total threads

    unsigned int local = 0;

    // Main loop: 4 stride-separated rows per iteration, all 12 loads
    // front-batched (independent -> MLP ~12). Access pattern per LDG stays
    // lane-contiguous (warp covers 1024B in 8 lines), keeping L1 wavefronts low.
    int i = gid;
    for (; i + 3 * S < batch; i += 4 * S) {
        int i0 = i, i1 = i + S, i2 = i + 2 * S, i3 = i + 3 * S;

        float4 a0 = preds[2 * i0],     a1 = preds[2 * i1];
        float4 a2 = preds[2 * i2],     a3 = preds[2 * i3];
        float4 b0 = preds[2 * i0 + 1], b1 = preds[2 * i1 + 1];
        float4 b2 = preds[2 * i2 + 1], b3 = preds[2 * i3 + 1];
        int t0 = targets[i0], t1 = targets[i1];
        int t2 = targets[i2], t3 = targets[i3];

        local += mismatch(a0, b0, t0);
        local += mismatch(a1, b1, t1);
        local += mismatch(a2, b2, t2);
        local += mismatch(a3, b3, t3);
    }
    // Tail: remaining rows grid-stride.
    for (; i < batch; i += S) {
        float4 a = preds[2 * i], b = preds[2 * i + 1];
        local += mismatch(a, b, targets[i]);
    }

    // warp reduction
    #pragma unroll
    for (int off = 16; off > 0; off >>= 1)
        local += __shfl_down_sync(0xFFFFFFFFu, local, off);

    __shared__ unsigned int warp_sums[8];
    int lane = threadIdx.x & 31;
    int wid = threadIdx.x >> 5;
    if (lane == 0) warp_sums[wid] = local;
    __syncthreads();

    if (wid == 0) {
        unsigned int v = (lane < (blockDim.x >> 5)) ? warp_sums[lane] : 0u;
        #pragma unroll
        for (int off = 4; off > 0; off >>= 1)
            v += __shfl_down_sync(0xFFFFFFFFu, v, off);

        if (lane == 0) {
            atomicAdd(&g_mismatch_count, (unsigned long long)v);
            __threadfence();
            unsigned int ticket = atomicAdd(&g_blocks_arrived, 1u);
            if (ticket == gridDim.x - 1) {
                unsigned long long total = atomicAdd(&g_mismatch_count, 0ULL);
                *out = (float)((double)total / (double)batch);
                g_mismatch_count = 0ULL;
                g_blocks_arrived = 0u;
            }
        }
    }
}

extern "C" void kernel_launch(void* const* d_in, const int* in_sizes, int n_in,
                              void* d_out, int out_size) {
    const float4* preds = (const float4*)d_in[0];   // [B, 8] f32
    const int* targets = (const int*)d_in[1];       // [B] int32
    int batch = in_sizes[0] / 8;
    float* out = (float*)d_out;

    const int threads = 256;
    int blocks = 4096;   // 1M threads; exactly one unrolled iter at B = 4.19M
    path_loss_fused_kernel<<<blocks, threads>>>(preds, targets, out, batch);
}